// round 5
// baseline (speedup 1.0000x reference)
#include <cuda_runtime.h>
#include <cstdint>

#define H 128
#define MAX_NODES 131072
#define TILE_N 64
#define WPAD 132   // 128 + 4 float pad, keeps float4 alignment, spreads banks

// Scratch (static device globals: allocation-free per harness rules)
__device__ __align__(16) static float g_S [(size_t)MAX_NODES * H];
__device__ __align__(16) static float g_I [(size_t)MAX_NODES * H];
__device__ __align__(16) static float g_AI[(size_t)MAX_NODES * H];
__device__ int g_is64;

// ---------------------------------------------------------------------------
// Index dtype probe: int64 data with values < 1e5 has all-zero high words.
// Random int32 row values in the odd slots being all zero has prob ~1e-320.
// ---------------------------------------------------------------------------
__global__ void detect_idx_kernel(const int* __restrict__ rows) {
    if (threadIdx.x == 0 && blockIdx.x == 0) {
        int all_hi_zero = 1;
        #pragma unroll 4
        for (int i = 0; i < 64; i++) {
            if (rows[2 * i + 1] != 0) { all_hi_zero = 0; break; }
        }
        g_is64 = all_hi_zero;
    }
}

// ---------------------------------------------------------------------------
// S/I = sigmoid(x[s] @ W^T + b), s in {0,1}.  out[n,o] = sum_h x[s,n,h]*W[o,h]
// Block: 256 threads, 64 nodes x 128 outputs. W transposed in smem (Ws[h][o]),
// each thread computes 4 nodes x 8 outputs with float4 loads/FMAs.
// ---------------------------------------------------------------------------
__global__ void __launch_bounds__(256) gemm_sigmoid_kernel(
    const float* __restrict__ x, const float* __restrict__ W,
    const float* __restrict__ b, int N)
{
    const int s = blockIdx.y;
    const float* __restrict__ xg = x + (size_t)s * N * H;
    float* __restrict__ out = (s == 0) ? g_S : g_I;

    extern __shared__ float sm[];
    float* Ws = sm;               // H * WPAD floats, transposed: Ws[h*WPAD + o]
    float* xt = sm + H * WPAD;    // TILE_N * H floats

    const int tid = threadIdx.x;

    // Load W (row-major [o][h]) -> transposed smem Ws[h][o]
    for (int i = tid; i < H * (H / 4); i += 256) {
        int o = i >> 5;            // 0..127
        int h4 = (i & 31) * 4;     // 0,4,...,124
        float4 w = ((const float4*)W)[i];
        Ws[(h4 + 0) * WPAD + o] = w.x;
        Ws[(h4 + 1) * WPAD + o] = w.y;
        Ws[(h4 + 2) * WPAD + o] = w.z;
        Ws[(h4 + 3) * WPAD + o] = w.w;
    }

    // Load x tile (64 nodes x 128), zero-padded past N
    const int n0 = blockIdx.x * TILE_N;
    for (int i = tid; i < TILE_N * (H / 4); i += 256) {
        int n = i >> 5;
        int q = i & 31;
        float4 v = make_float4(0.f, 0.f, 0.f, 0.f);
        if (n0 + n < N) v = ((const float4*)(xg + (size_t)(n0 + n) * H))[q];
        ((float4*)xt)[n * 32 + q] = v;
    }
    __syncthreads();

    const int ot = tid & 15;           // output-group thread
    const int nt = tid >> 4;           // node-group thread
    const int o_base = ot * 8;
    const int n_base = nt * 4;

    float4 acc[4][2];
    #pragma unroll
    for (int j = 0; j < 4; j++) {
        acc[j][0] = make_float4(0.f, 0.f, 0.f, 0.f);
        acc[j][1] = make_float4(0.f, 0.f, 0.f, 0.f);
    }

    #pragma unroll 4
    for (int h = 0; h < H; h += 4) {
        float4 xv[4];
        #pragma unroll
        for (int j = 0; j < 4; j++)
            xv[j] = ((const float4*)xt)[(n_base + j) * 32 + (h >> 2)];
        #pragma unroll
        for (int c = 0; c < 4; c++) {
            const float4 w0 = *(const float4*)&Ws[(h + c) * WPAD + o_base];
            const float4 w1 = *(const float4*)&Ws[(h + c) * WPAD + o_base + 4];
            #pragma unroll
            for (int j = 0; j < 4; j++) {
                float xc = (c == 0) ? xv[j].x : (c == 1) ? xv[j].y
                         : (c == 2) ? xv[j].z : xv[j].w;
                acc[j][0].x = fmaf(xc, w0.x, acc[j][0].x);
                acc[j][0].y = fmaf(xc, w0.y, acc[j][0].y);
                acc[j][0].z = fmaf(xc, w0.z, acc[j][0].z);
                acc[j][0].w = fmaf(xc, w0.w, acc[j][0].w);
                acc[j][1].x = fmaf(xc, w1.x, acc[j][1].x);
                acc[j][1].y = fmaf(xc, w1.y, acc[j][1].y);
                acc[j][1].z = fmaf(xc, w1.z, acc[j][1].z);
                acc[j][1].w = fmaf(xc, w1.w, acc[j][1].w);
            }
        }
    }

    const float4 b0 = ((const float4*)b)[ot * 2];
    const float4 b1 = ((const float4*)b)[ot * 2 + 1];

    #pragma unroll
    for (int j = 0; j < 4; j++) {
        int node = n0 + n_base + j;
        if (node >= N) continue;
        float4 r0, r1;
        r0.x = 1.f / (1.f + __expf(-(acc[j][0].x + b0.x)));
        r0.y = 1.f / (1.f + __expf(-(acc[j][0].y + b0.y)));
        r0.z = 1.f / (1.f + __expf(-(acc[j][0].z + b0.z)));
        r0.w = 1.f / (1.f + __expf(-(acc[j][0].w + b0.w)));
        r1.x = 1.f / (1.f + __expf(-(acc[j][1].x + b1.x)));
        r1.y = 1.f / (1.f + __expf(-(acc[j][1].y + b1.y)));
        r1.z = 1.f / (1.f + __expf(-(acc[j][1].z + b1.z)));
        r1.w = 1.f / (1.f + __expf(-(acc[j][1].w + b1.w)));
        float4* dst = (float4*)(out + (size_t)node * H + o_base);
        dst[0] = r0;
        dst[1] = r1;
    }
}

// ---------------------------------------------------------------------------
// Edge scatter: AI[rows[e]] += I[cols[e]].  One warp per edge, one 16B
// vectorized red.global per lane (4x fewer atomic ops than scalar).
// Working set (I + AI = 102MB) is L2-resident.
// ---------------------------------------------------------------------------
__global__ void __launch_bounds__(256) scatter_kernel(
    const void* __restrict__ rows, const void* __restrict__ cols, int nE)
{
    const int g = blockIdx.x * 256 + threadIdx.x;
    const int e = g >> 5;
    const int lane = g & 31;
    if (e >= nE) return;

    long long r, c;
    if (g_is64) {
        r = ((const long long*)rows)[e];
        c = ((const long long*)cols)[e];
    } else {
        r = ((const int*)rows)[e];
        c = ((const int*)cols)[e];
    }

    const float4 v = ((const float4*)(g_I + (size_t)c * H))[lane];
    float* dst = g_AI + (size_t)r * H + lane * 4;
    asm volatile("red.global.add.v4.f32 [%0], {%1,%2,%3,%4};"
                 :: "l"(dst), "f"(v.x), "f"(v.y), "f"(v.z), "f"(v.w)
                 : "memory");
}

// ---------------------------------------------------------------------------
// Epilogue: dS = -beta*AI*S; dI = -dS - gamma*I; dR = gamma*I; out[3] = 0
// ---------------------------------------------------------------------------
__global__ void __launch_bounds__(256) epilogue_kernel(
    const float* __restrict__ x, float* __restrict__ out, int N)
{
    const int idx = blockIdx.x * 256 + threadIdx.x;   // float4 units
    const int total = N * (H / 4);
    if (idx >= total) return;
    const int n = idx >> 5;

    const float* x3 = x + (size_t)3 * N * H + (size_t)n * H;
    const float beta  = x3[0];
    const float gamma = x3[1];

    const float4 ai = ((const float4*)g_AI)[idx];
    const float4 sv = ((const float4*)g_S)[idx];
    const float4 iv = ((const float4*)g_I)[idx];

    float4 dS, dI, dR;
    dS.x = -beta * ai.x * sv.x;  dS.y = -beta * ai.y * sv.y;
    dS.z = -beta * ai.z * sv.z;  dS.w = -beta * ai.w * sv.w;
    dR.x = gamma * iv.x;  dR.y = gamma * iv.y;
    dR.z = gamma * iv.z;  dR.w = gamma * iv.w;
    dI.x = -dS.x - dR.x;  dI.y = -dS.y - dR.y;
    dI.z = -dS.z - dR.z;  dI.w = -dS.w - dR.w;

    const size_t NH4 = (size_t)N * (H / 4);
    float4* o4 = (float4*)out;
    o4[idx]            = dS;
    o4[NH4 + idx]      = dI;
    o4[2 * NH4 + idx]  = dR;
    o4[3 * NH4 + idx]  = make_float4(0.f, 0.f, 0.f, 0.f);
}

// ---------------------------------------------------------------------------
extern "C" void kernel_launch(void* const* d_in, const int* in_sizes, int n_in,
                              void* d_out, int out_size)
{
    const float* x    = (const float*)d_in[0];
    const float* W    = (const float*)d_in[1];
    const float* b    = (const float*)d_in[2];
    const void*  rows = d_in[3];
    const void*  cols = d_in[4];

    const int N  = in_sizes[0] / (4 * H);
    const int nE = in_sizes[3];

    // Zero the accumulator (graph-capturable memset node)
    void* aiPtr = nullptr;
    cudaGetSymbolAddress(&aiPtr, g_AI);
    cudaMemsetAsync(aiPtr, 0, (size_t)N * H * sizeof(float));

    detect_idx_kernel<<<1, 32>>>((const int*)rows);

    const int smem_bytes = (H * WPAD + TILE_N * H) * (int)sizeof(float);
    cudaFuncSetAttribute(gemm_sigmoid_kernel,
                         cudaFuncAttributeMaxDynamicSharedMemorySize, smem_bytes);
    dim3 ggrid((N + TILE_N - 1) / TILE_N, 2);
    gemm_sigmoid_kernel<<<ggrid, 256, smem_bytes>>>(x, W, b, N);

    const long long scatter_threads = (long long)nE * 32;
    scatter_kernel<<<(int)((scatter_threads + 255) / 256), 256>>>(rows, cols, nE);

    const int ep_total = N * (H / 4);
    epilogue_kernel<<<(ep_total + 255) / 256, 256>>>(x, (float*)d_out, N);
}

// round 6
// speedup vs baseline: 1.2389x; 1.2389x over previous
#include <cuda_runtime.h>
#include <cstdint>

#define H 128
#define MAX_NODES 131072
#define MAX_EDGES 2097152
#define TILE_N 64
#define WPAD 132   // 128 + 4 float pad: float4-aligned rows, spread banks

// Scratch (static device globals: allocation-free per harness rules)
__device__ __align__(16) static float g_S [(size_t)MAX_NODES * H];
__device__ __align__(16) static float g_I [(size_t)MAX_NODES * H];
__device__ static int g_cnt   [MAX_NODES];
__device__ static int g_off   [MAX_NODES];
__device__ static int g_cursor[MAX_NODES];
__device__ static int g_ecol  [MAX_EDGES];
__device__ static int g_bsum  [1024];
__device__ int g_is64;

// ---------------------------------------------------------------------------
// f32x2 packed-FMA helpers (PTX-only pattern; ptxas never auto-fuses)
// ---------------------------------------------------------------------------
__device__ __forceinline__ uint64_t pack2(float a) {
    uint64_t r;
    asm("mov.b64 %0, {%1, %1};" : "=l"(r) : "f"(a));
    return r;
}
__device__ __forceinline__ void ffma2(uint64_t& d, uint64_t a, uint64_t b) {
    asm("fma.rn.f32x2 %0, %1, %2, %0;" : "+l"(d) : "l"(a), "l"(b));
}
__device__ __forceinline__ float2 unpack2(uint64_t v) {
    float2 r;
    asm("mov.b64 {%0, %1}, %2;" : "=f"(r.x), "=f"(r.y) : "l"(v));
    return r;
}

// ---------------------------------------------------------------------------
// Index dtype probe: int64 values < 1e5 have all-zero high words.
// ---------------------------------------------------------------------------
__global__ void detect_idx_kernel(const int* __restrict__ rows) {
    if (threadIdx.x == 0 && blockIdx.x == 0) {
        int all_hi_zero = 1;
        #pragma unroll 4
        for (int i = 0; i < 64; i++) {
            if (rows[2 * i + 1] != 0) { all_hi_zero = 0; break; }
        }
        g_is64 = all_hi_zero;
    }
}

__device__ __forceinline__ int load_idx(const void* p, int e) {
    return g_is64 ? (int)((const long long*)p)[e] : ((const int*)p)[e];
}

// ---------------------------------------------------------------------------
// CSR build: histogram -> 2-level exclusive scan -> fill
// ---------------------------------------------------------------------------
__global__ void __launch_bounds__(256) hist_kernel(const void* __restrict__ rows, int nE) {
    int e = blockIdx.x * 256 + threadIdx.x;
    if (e >= nE) return;
    atomicAdd(&g_cnt[load_idx(rows, e)], 1);
}

__global__ void __launch_bounds__(1024) scan1_kernel(int N) {
    __shared__ int sm[1024];
    int i = blockIdx.x * 1024 + threadIdx.x;
    int v = (i < N) ? g_cnt[i] : 0;
    sm[threadIdx.x] = v;
    __syncthreads();
    #pragma unroll
    for (int d = 1; d < 1024; d <<= 1) {
        int t = (threadIdx.x >= d) ? sm[threadIdx.x - d] : 0;
        __syncthreads();
        sm[threadIdx.x] += t;
        __syncthreads();
    }
    if (i < N) g_off[i] = sm[threadIdx.x] - v;       // exclusive
    if (threadIdx.x == 1023) g_bsum[blockIdx.x] = sm[1023];
}

__global__ void __launch_bounds__(1024) scan2_kernel(int nb) {
    __shared__ int sm[1024];
    int v = (threadIdx.x < nb) ? g_bsum[threadIdx.x] : 0;
    sm[threadIdx.x] = v;
    __syncthreads();
    #pragma unroll
    for (int d = 1; d < 1024; d <<= 1) {
        int t = (threadIdx.x >= d) ? sm[threadIdx.x - d] : 0;
        __syncthreads();
        sm[threadIdx.x] += t;
        __syncthreads();
    }
    if (threadIdx.x < nb) g_bsum[threadIdx.x] = sm[threadIdx.x] - v;  // exclusive
}

__global__ void __launch_bounds__(1024) scan3_kernel(int N) {
    int i = blockIdx.x * 1024 + threadIdx.x;
    if (i >= N) return;
    int o = g_off[i] + g_bsum[i >> 10];
    g_off[i] = o;
    g_cursor[i] = o;
}

__global__ void __launch_bounds__(256) fill_kernel(
    const void* __restrict__ rows, const void* __restrict__ cols, int nE)
{
    int e = blockIdx.x * 256 + threadIdx.x;
    if (e >= nE) return;
    int r = load_idx(rows, e);
    int c = load_idx(cols, e);
    int p = atomicAdd(&g_cursor[r], 1);
    g_ecol[p] = c;
}

// ---------------------------------------------------------------------------
// S/I = sigmoid(x[s] @ W^T + b).  64 nodes x 128 outputs per 256-thread block;
// each thread 4 nodes x 8 outputs via packed f32x2 FMAs (2x fp32 rate).
// ---------------------------------------------------------------------------
__global__ void __launch_bounds__(256) gemm_sigmoid_kernel(
    const float* __restrict__ x, const float* __restrict__ W,
    const float* __restrict__ b, int N)
{
    const int s = blockIdx.y;
    const float* __restrict__ xg = x + (size_t)s * N * H;
    float* __restrict__ out = (s == 0) ? g_S : g_I;

    extern __shared__ float sm[];
    float* Ws = sm;               // H * WPAD, transposed: Ws[h*WPAD + o]
    float* xt = sm + H * WPAD;    // TILE_N * H

    const int tid = threadIdx.x;

    for (int i = tid; i < H * (H / 4); i += 256) {
        int o = i >> 5;
        int h4 = (i & 31) * 4;
        float4 w = ((const float4*)W)[i];
        Ws[(h4 + 0) * WPAD + o] = w.x;
        Ws[(h4 + 1) * WPAD + o] = w.y;
        Ws[(h4 + 2) * WPAD + o] = w.z;
        Ws[(h4 + 3) * WPAD + o] = w.w;
    }

    const int n0 = blockIdx.x * TILE_N;
    for (int i = tid; i < TILE_N * (H / 4); i += 256) {
        int n = i >> 5;
        int q = i & 31;
        float4 v = make_float4(0.f, 0.f, 0.f, 0.f);
        if (n0 + n < N) v = ((const float4*)(xg + (size_t)(n0 + n) * H))[q];
        ((float4*)xt)[n * 32 + q] = v;
    }
    __syncthreads();

    const int ot = tid & 15;
    const int nt = tid >> 4;
    const int o_base = ot * 8;
    const int n_base = nt * 4;

    uint64_t acc2[4][4];
    #pragma unroll
    for (int j = 0; j < 4; j++)
        #pragma unroll
        for (int k = 0; k < 4; k++) acc2[j][k] = 0ull;

    #pragma unroll 2
    for (int h = 0; h < H; h += 4) {
        float4 xv[4];
        #pragma unroll
        for (int j = 0; j < 4; j++)
            xv[j] = ((const float4*)xt)[(n_base + j) * 32 + (h >> 2)];
        #pragma unroll
        for (int c = 0; c < 4; c++) {
            const ulonglong2* wp = (const ulonglong2*)&Ws[(h + c) * WPAD + o_base];
            const ulonglong2 wA = wp[0];
            const ulonglong2 wB = wp[1];
            #pragma unroll
            for (int j = 0; j < 4; j++) {
                float xc = (c == 0) ? xv[j].x : (c == 1) ? xv[j].y
                         : (c == 2) ? xv[j].z : xv[j].w;
                uint64_t xp = pack2(xc);
                ffma2(acc2[j][0], xp, wA.x);
                ffma2(acc2[j][1], xp, wA.y);
                ffma2(acc2[j][2], xp, wB.x);
                ffma2(acc2[j][3], xp, wB.y);
            }
        }
    }

    const float4 b0 = ((const float4*)b)[ot * 2];
    const float4 b1 = ((const float4*)b)[ot * 2 + 1];

    #pragma unroll
    for (int j = 0; j < 4; j++) {
        int node = n0 + n_base + j;
        if (node >= N) continue;
        float2 a0 = unpack2(acc2[j][0]);
        float2 a1 = unpack2(acc2[j][1]);
        float2 a2 = unpack2(acc2[j][2]);
        float2 a3 = unpack2(acc2[j][3]);
        float4 r0, r1;
        r0.x = 1.f / (1.f + __expf(-(a0.x + b0.x)));
        r0.y = 1.f / (1.f + __expf(-(a0.y + b0.y)));
        r0.z = 1.f / (1.f + __expf(-(a1.x + b0.z)));
        r0.w = 1.f / (1.f + __expf(-(a1.y + b0.w)));
        r1.x = 1.f / (1.f + __expf(-(a2.x + b1.x)));
        r1.y = 1.f / (1.f + __expf(-(a2.y + b1.y)));
        r1.z = 1.f / (1.f + __expf(-(a3.x + b1.z)));
        r1.w = 1.f / (1.f + __expf(-(a3.y + b1.w)));
        float4* dst = (float4*)(out + (size_t)node * H + o_base);
        dst[0] = r0;
        dst[1] = r1;
    }
}

// ---------------------------------------------------------------------------
// Fused gather + epilogue: one warp per destination row.  Accumulate
// AI[row] = sum_{e in CSR[row]} I[col_e] in registers (no atomics), then
// compute dS/dI/dR and write out directly.  AI never touches memory.
// ---------------------------------------------------------------------------
__global__ void __launch_bounds__(256) gather_epilogue_kernel(
    const float* __restrict__ x, float* __restrict__ out, int N)
{
    const int g = blockIdx.x * 256 + threadIdx.x;
    const int row = g >> 5;
    const int lane = g & 31;
    if (row >= N) return;

    const int start = g_off[row];
    const int deg   = g_cnt[row];
    const float4* __restrict__ Ib = (const float4*)g_I;

    float4 ai = make_float4(0.f, 0.f, 0.f, 0.f);
    int e = 0;
    for (; e + 4 <= deg; e += 4) {
        const int c0 = g_ecol[start + e + 0];
        const int c1 = g_ecol[start + e + 1];
        const int c2 = g_ecol[start + e + 2];
        const int c3 = g_ecol[start + e + 3];
        const float4 v0 = Ib[(size_t)c0 * 32 + lane];
        const float4 v1 = Ib[(size_t)c1 * 32 + lane];
        const float4 v2 = Ib[(size_t)c2 * 32 + lane];
        const float4 v3 = Ib[(size_t)c3 * 32 + lane];
        ai.x += (v0.x + v1.x) + (v2.x + v3.x);
        ai.y += (v0.y + v1.y) + (v2.y + v3.y);
        ai.z += (v0.z + v1.z) + (v2.z + v3.z);
        ai.w += (v0.w + v1.w) + (v2.w + v3.w);
    }
    for (; e < deg; e++) {
        const int c = g_ecol[start + e];
        const float4 v = Ib[(size_t)c * 32 + lane];
        ai.x += v.x; ai.y += v.y; ai.z += v.z; ai.w += v.w;
    }

    const float* x3 = x + (size_t)3 * N * H + (size_t)row * H;
    const float beta  = x3[0];
    const float gamma = x3[1];

    const size_t r32 = (size_t)row * 32 + lane;
    const float4 sv = ((const float4*)g_S)[r32];
    const float4 iv = Ib[r32];

    float4 dS, dI, dR;
    dS.x = -beta * ai.x * sv.x;  dS.y = -beta * ai.y * sv.y;
    dS.z = -beta * ai.z * sv.z;  dS.w = -beta * ai.w * sv.w;
    dR.x = gamma * iv.x;  dR.y = gamma * iv.y;
    dR.z = gamma * iv.z;  dR.w = gamma * iv.w;
    dI.x = -dS.x - dR.x;  dI.y = -dS.y - dR.y;
    dI.z = -dS.z - dR.z;  dI.w = -dS.w - dR.w;

    const size_t NH4 = (size_t)N * 32;
    float4* o4 = (float4*)out;
    o4[r32]           = dS;
    o4[NH4 + r32]     = dI;
    o4[2 * NH4 + r32] = dR;
    o4[3 * NH4 + r32] = make_float4(0.f, 0.f, 0.f, 0.f);
}

// ---------------------------------------------------------------------------
extern "C" void kernel_launch(void* const* d_in, const int* in_sizes, int n_in,
                              void* d_out, int out_size)
{
    const float* x    = (const float*)d_in[0];
    const float* W    = (const float*)d_in[1];
    const float* b    = (const float*)d_in[2];
    const void*  rows = d_in[3];
    const void*  cols = d_in[4];

    const int N  = in_sizes[0] / (4 * H);
    const int nE = in_sizes[3];

    void* cntPtr = nullptr;
    cudaGetSymbolAddress(&cntPtr, g_cnt);
    cudaMemsetAsync(cntPtr, 0, (size_t)N * sizeof(int));

    detect_idx_kernel<<<1, 32>>>((const int*)rows);

    // GEMM (overlappable with CSR build on the same stream? keep serial —
    // launch GEMM first so its long tail overlaps nothing it depends on)
    const int smem_bytes = (H * WPAD + TILE_N * H) * (int)sizeof(float);
    cudaFuncSetAttribute(gemm_sigmoid_kernel,
                         cudaFuncAttributeMaxDynamicSharedMemorySize, smem_bytes);
    dim3 ggrid((N + TILE_N - 1) / TILE_N, 2);
    gemm_sigmoid_kernel<<<ggrid, 256, smem_bytes>>>(x, W, b, N);

    // CSR build
    const int eb = (nE + 255) / 256;
    hist_kernel<<<eb, 256>>>(rows, nE);
    const int nb = (N + 1023) / 1024;
    scan1_kernel<<<nb, 1024>>>(N);
    scan2_kernel<<<1, 1024>>>(nb);
    scan3_kernel<<<nb, 1024>>>(N);
    fill_kernel<<<eb, 256>>>(rows, cols, nE);

    // Fused gather + epilogue (one warp per row)
    const long long gt = (long long)N * 32;
    gather_epilogue_kernel<<<(int)((gt + 255) / 256), 256>>>(x, (float*)d_out, N);
}

// round 7
// speedup vs baseline: 1.2909x; 1.0420x over previous
#include <cuda_runtime.h>
#include <cuda_fp16.h>
#include <cstdint>

#define H 128
#define MAX_NODES 131072
#define MAX_EDGES 2097152
#define TILE_N 64
#define WPAD 132   // 128 + 4 float pad: float4-aligned rows, spread banks

// Scratch (static device globals: allocation-free per harness rules)
__device__ __align__(16) static float  g_S [(size_t)MAX_NODES * H];
__device__ __align__(16) static float  g_I [(size_t)MAX_NODES * H];
__device__ __align__(16) static __half g_Ih[(size_t)MAX_NODES * H];  // fp16 copy for gather
__device__ static int g_cnt   [MAX_NODES];
__device__ static int g_off   [MAX_NODES];
__device__ static int g_cursor[MAX_NODES];
__device__ static int g_ecol  [MAX_EDGES];
__device__ static int g_bsum  [1024];
__device__ int g_is64;

// ---------------------------------------------------------------------------
// f32x2 packed-FMA helpers (PTX-only; ptxas never auto-fuses)
// ---------------------------------------------------------------------------
__device__ __forceinline__ uint64_t pack2(float a) {
    uint64_t r;
    asm("mov.b64 %0, {%1, %1};" : "=l"(r) : "f"(a));
    return r;
}
__device__ __forceinline__ void ffma2(uint64_t& d, uint64_t a, uint64_t b) {
    asm("fma.rn.f32x2 %0, %1, %2, %0;" : "+l"(d) : "l"(a), "l"(b));
}
__device__ __forceinline__ float2 unpack2(uint64_t v) {
    float2 r;
    asm("mov.b64 {%0, %1}, %2;" : "=f"(r.x), "=f"(r.y) : "l"(v));
    return r;
}

// ---------------------------------------------------------------------------
// Index dtype probe: int64 values < 1e5 have all-zero high words.
// ---------------------------------------------------------------------------
__global__ void detect_idx_kernel(const int* __restrict__ rows) {
    if (threadIdx.x == 0 && blockIdx.x == 0) {
        int all_hi_zero = 1;
        #pragma unroll 4
        for (int i = 0; i < 64; i++) {
            if (rows[2 * i + 1] != 0) { all_hi_zero = 0; break; }
        }
        g_is64 = all_hi_zero;
    }
}

__device__ __forceinline__ int load_idx(const void* p, int e) {
    return g_is64 ? (int)((const long long*)p)[e] : ((const int*)p)[e];
}

// ---------------------------------------------------------------------------
// CSR build: histogram -> 2-level exclusive scan -> fill
// ---------------------------------------------------------------------------
__global__ void __launch_bounds__(256) hist_kernel(const void* __restrict__ rows, int nE) {
    int e = blockIdx.x * 256 + threadIdx.x;
    if (e >= nE) return;
    atomicAdd(&g_cnt[load_idx(rows, e)], 1);
}

__global__ void __launch_bounds__(1024) scan1_kernel(int N) {
    __shared__ int sm[1024];
    int i = blockIdx.x * 1024 + threadIdx.x;
    int v = (i < N) ? g_cnt[i] : 0;
    sm[threadIdx.x] = v;
    __syncthreads();
    #pragma unroll
    for (int d = 1; d < 1024; d <<= 1) {
        int t = (threadIdx.x >= d) ? sm[threadIdx.x - d] : 0;
        __syncthreads();
        sm[threadIdx.x] += t;
        __syncthreads();
    }
    if (i < N) g_off[i] = sm[threadIdx.x] - v;       // exclusive
    if (threadIdx.x == 1023) g_bsum[blockIdx.x] = sm[1023];
}

__global__ void __launch_bounds__(1024) scan2_kernel(int nb) {
    __shared__ int sm[1024];
    int v = (threadIdx.x < nb) ? g_bsum[threadIdx.x] : 0;
    sm[threadIdx.x] = v;
    __syncthreads();
    #pragma unroll
    for (int d = 1; d < 1024; d <<= 1) {
        int t = (threadIdx.x >= d) ? sm[threadIdx.x - d] : 0;
        __syncthreads();
        sm[threadIdx.x] += t;
        __syncthreads();
    }
    if (threadIdx.x < nb) g_bsum[threadIdx.x] = sm[threadIdx.x] - v;  // exclusive
}

__global__ void __launch_bounds__(1024) scan3_kernel(int N) {
    int i = blockIdx.x * 1024 + threadIdx.x;
    if (i >= N) return;
    int o = g_off[i] + g_bsum[i >> 10];
    g_off[i] = o;
    g_cursor[i] = o;
}

__global__ void __launch_bounds__(256) fill_kernel(
    const void* __restrict__ rows, const void* __restrict__ cols, int nE)
{
    int e = blockIdx.x * 256 + threadIdx.x;
    if (e >= nE) return;
    int r = load_idx(rows, e);
    int c = load_idx(cols, e);
    int p = atomicAdd(&g_cursor[r], 1);
    g_ecol[p] = c;
}

// ---------------------------------------------------------------------------
// S/I = sigmoid(x[s] @ W^T + b) via packed f32x2 FMAs.  For s==1, also emit
// an fp16 copy (g_Ih) used by the gather: halves traffic, fits L2.
// fp32 S/I stores use __stcs (read exactly once later, coalesced).
// ---------------------------------------------------------------------------
__global__ void __launch_bounds__(256) gemm_sigmoid_kernel(
    const float* __restrict__ x, const float* __restrict__ W,
    const float* __restrict__ b, int N)
{
    const int s = blockIdx.y;
    const float* __restrict__ xg = x + (size_t)s * N * H;
    float* __restrict__ out = (s == 0) ? g_S : g_I;

    extern __shared__ float sm[];
    float* Ws = sm;               // H * WPAD, transposed: Ws[h*WPAD + o]
    float* xt = sm + H * WPAD;    // TILE_N * H

    const int tid = threadIdx.x;

    for (int i = tid; i < H * (H / 4); i += 256) {
        int o = i >> 5;
        int h4 = (i & 31) * 4;
        float4 w = ((const float4*)W)[i];
        Ws[(h4 + 0) * WPAD + o] = w.x;
        Ws[(h4 + 1) * WPAD + o] = w.y;
        Ws[(h4 + 2) * WPAD + o] = w.z;
        Ws[(h4 + 3) * WPAD + o] = w.w;
    }

    const int n0 = blockIdx.x * TILE_N;
    for (int i = tid; i < TILE_N * (H / 4); i += 256) {
        int n = i >> 5;
        int q = i & 31;
        float4 v = make_float4(0.f, 0.f, 0.f, 0.f);
        if (n0 + n < N)
            v = __ldcs((const float4*)(xg + (size_t)(n0 + n) * H) + q);  // read-once
        ((float4*)xt)[n * 32 + q] = v;
    }
    __syncthreads();

    const int ot = tid & 15;
    const int nt = tid >> 4;
    const int o_base = ot * 8;
    const int n_base = nt * 4;

    uint64_t acc2[4][4];
    #pragma unroll
    for (int j = 0; j < 4; j++)
        #pragma unroll
        for (int k = 0; k < 4; k++) acc2[j][k] = 0ull;

    #pragma unroll 2
    for (int h = 0; h < H; h += 4) {
        float4 xv[4];
        #pragma unroll
        for (int j = 0; j < 4; j++)
            xv[j] = ((const float4*)xt)[(n_base + j) * 32 + (h >> 2)];
        #pragma unroll
        for (int c = 0; c < 4; c++) {
            const ulonglong2* wp = (const ulonglong2*)&Ws[(h + c) * WPAD + o_base];
            const ulonglong2 wA = wp[0];
            const ulonglong2 wB = wp[1];
            #pragma unroll
            for (int j = 0; j < 4; j++) {
                float xc = (c == 0) ? xv[j].x : (c == 1) ? xv[j].y
                         : (c == 2) ? xv[j].z : xv[j].w;
                uint64_t xp = pack2(xc);
                ffma2(acc2[j][0], xp, wA.x);
                ffma2(acc2[j][1], xp, wA.y);
                ffma2(acc2[j][2], xp, wB.x);
                ffma2(acc2[j][3], xp, wB.y);
            }
        }
    }

    const float4 b0 = ((const float4*)b)[ot * 2];
    const float4 b1 = ((const float4*)b)[ot * 2 + 1];

    #pragma unroll
    for (int j = 0; j < 4; j++) {
        int node = n0 + n_base + j;
        if (node >= N) continue;
        float2 a0 = unpack2(acc2[j][0]);
        float2 a1 = unpack2(acc2[j][1]);
        float2 a2 = unpack2(acc2[j][2]);
        float2 a3 = unpack2(acc2[j][3]);
        float4 r0, r1;
        r0.x = 1.f / (1.f + __expf(-(a0.x + b0.x)));
        r0.y = 1.f / (1.f + __expf(-(a0.y + b0.y)));
        r0.z = 1.f / (1.f + __expf(-(a1.x + b0.z)));
        r0.w = 1.f / (1.f + __expf(-(a1.y + b0.w)));
        r1.x = 1.f / (1.f + __expf(-(a2.x + b1.x)));
        r1.y = 1.f / (1.f + __expf(-(a2.y + b1.y)));
        r1.z = 1.f / (1.f + __expf(-(a3.x + b1.z)));
        r1.w = 1.f / (1.f + __expf(-(a3.y + b1.w)));
        float4* dst = (float4*)(out + (size_t)node * H + o_base);
        __stcs(dst,     r0);   // fp32 copy: read once (coalesced), evict-first
        __stcs(dst + 1, r1);
        if (s == 1) {
            // fp16 copy for the gather hot path (keep L2-resident: normal policy)
            __half2 ha = __floats2half2_rn(r0.x, r0.y);
            __half2 hb = __floats2half2_rn(r0.z, r0.w);
            __half2 hc = __floats2half2_rn(r1.x, r1.y);
            __half2 hd = __floats2half2_rn(r1.z, r1.w);
            uint4 p;
            p.x = *(unsigned*)&ha;  p.y = *(unsigned*)&hb;
            p.z = *(unsigned*)&hc;  p.w = *(unsigned*)&hd;
            ((uint4*)g_Ih)[(size_t)node * 16 + ot] = p;
        }
    }
}

// ---------------------------------------------------------------------------
// Fused gather + epilogue: one warp per destination row.  AI accumulated in
// registers from the fp16 I copy (256B/edge instead of 512B); dS/dI/dR
// computed in-register and streamed out with evict-first stores.
// ---------------------------------------------------------------------------
__global__ void __launch_bounds__(256) gather_epilogue_kernel(
    const float* __restrict__ x, float* __restrict__ out, int N)
{
    const int g = blockIdx.x * 256 + threadIdx.x;
    const int row = g >> 5;
    const int lane = g & 31;
    if (row >= N) return;

    const int start = g_off[row];
    const int deg   = g_cnt[row];
    const uint2* __restrict__ Ih = (const uint2*)g_Ih;   // 32 uint2 per row (4 halves each)

    float4 ai = make_float4(0.f, 0.f, 0.f, 0.f);
    int e = 0;
    for (; e + 4 <= deg; e += 4) {
        const int c0 = __ldcs(&g_ecol[start + e + 0]);
        const int c1 = __ldcs(&g_ecol[start + e + 1]);
        const int c2 = __ldcs(&g_ecol[start + e + 2]);
        const int c3 = __ldcs(&g_ecol[start + e + 3]);
        const uint2 v0 = Ih[(size_t)c0 * 32 + lane];
        const uint2 v1 = Ih[(size_t)c1 * 32 + lane];
        const uint2 v2 = Ih[(size_t)c2 * 32 + lane];
        const uint2 v3 = Ih[(size_t)c3 * 32 + lane];
        #pragma unroll
        for (int k = 0; k < 4; k++) {
            const uint2 v = (k == 0) ? v0 : (k == 1) ? v1 : (k == 2) ? v2 : v3;
            const float2 f0 = __half22float2(*(const __half2*)&v.x);
            const float2 f1 = __half22float2(*(const __half2*)&v.y);
            ai.x += f0.x; ai.y += f0.y; ai.z += f1.x; ai.w += f1.y;
        }
    }
    for (; e < deg; e++) {
        const int c = __ldcs(&g_ecol[start + e]);
        const uint2 v = Ih[(size_t)c * 32 + lane];
        const float2 f0 = __half22float2(*(const __half2*)&v.x);
        const float2 f1 = __half22float2(*(const __half2*)&v.y);
        ai.x += f0.x; ai.y += f0.y; ai.z += f1.x; ai.w += f1.y;
    }

    const float* x3 = x + (size_t)3 * N * H + (size_t)row * H;
    const float beta  = x3[0];
    const float gamma = x3[1];

    const size_t r32 = (size_t)row * 32 + lane;
    const float4 sv = __ldcs((const float4*)g_S + r32);  // read-once
    const float4 iv = __ldcs((const float4*)g_I + r32);  // read-once (fp32 copy)

    float4 dS, dI, dR;
    dS.x = -beta * ai.x * sv.x;  dS.y = -beta * ai.y * sv.y;
    dS.z = -beta * ai.z * sv.z;  dS.w = -beta * ai.w * sv.w;
    dR.x = gamma * iv.x;  dR.y = gamma * iv.y;
    dR.z = gamma * iv.z;  dR.w = gamma * iv.w;
    dI.x = -dS.x - dR.x;  dI.y = -dS.y - dR.y;
    dI.z = -dS.z - dR.z;  dI.w = -dS.w - dR.w;

    const size_t NH4 = (size_t)N * 32;
    float4* o4 = (float4*)out;
    __stcs(o4 + r32,           dS);   // streaming, evict-first: protect I_h in L2
    __stcs(o4 + NH4 + r32,     dI);
    __stcs(o4 + 2 * NH4 + r32, dR);
    __stcs(o4 + 3 * NH4 + r32, make_float4(0.f, 0.f, 0.f, 0.f));
}

// ---------------------------------------------------------------------------
extern "C" void kernel_launch(void* const* d_in, const int* in_sizes, int n_in,
                              void* d_out, int out_size)
{
    const float* x    = (const float*)d_in[0];
    const float* W    = (const float*)d_in[1];
    const float* b    = (const float*)d_in[2];
    const void*  rows = d_in[3];
    const void*  cols = d_in[4];

    const int N  = in_sizes[0] / (4 * H);
    const int nE = in_sizes[3];

    void* cntPtr = nullptr;
    cudaGetSymbolAddress(&cntPtr, g_cnt);
    cudaMemsetAsync(cntPtr, 0, (size_t)N * sizeof(int));      // item 1

    detect_idx_kernel<<<1, 32>>>((const int*)rows);           // item 2

    const int eb = (nE + 255) / 256;
    const int nb = (N + 1023) / 1024;
    hist_kernel<<<eb, 256>>>(rows, nE);                       // item 3
    scan1_kernel<<<nb, 1024>>>(N);                            // item 4

    // GEMM at profiled slot 5 (independent of CSR kernels; serial stream keeps deps)
    const int smem_bytes = (H * WPAD + TILE_N * H) * (int)sizeof(float);
    cudaFuncSetAttribute(gemm_sigmoid_kernel,
                         cudaFuncAttributeMaxDynamicSharedMemorySize, smem_bytes);
    dim3 ggrid((N + TILE_N - 1) / TILE_N, 2);
    gemm_sigmoid_kernel<<<ggrid, 256, smem_bytes>>>(x, W, b, N);  // item 5

    scan2_kernel<<<1, 1024>>>(nb);                            // item 6
    scan3_kernel<<<nb, 1024>>>(N);                            // item 7
    fill_kernel<<<eb, 256>>>(rows, cols, nE);                 // item 8

    const long long gt = (long long)N * 32;
    gather_epilogue_kernel<<<(int)((gt + 255) / 256), 256>>>(x, (float*)d_out, N);
}

// round 8
// speedup vs baseline: 2.3033x; 1.7843x over previous
#include <cuda_runtime.h>
#include <cuda_fp16.h>
#include <cstdint>

#define H 128
#define MAX_NODES 131072
#define MAX_EDGES 2097152
#define XPITCH 132   // xt pitch: A-frag banks g*4+c -> conflict-free
#define WPITCH 132   // W row-major pitch: B-frag banks g*4+c -> conflict-free

// Scratch (static device globals: allocation-free per harness rules)
__device__ __align__(16) static float  g_S [(size_t)MAX_NODES * H];
__device__ __align__(16) static float  g_I [(size_t)MAX_NODES * H];
__device__ __align__(16) static __half g_Ih[(size_t)MAX_NODES * H];  // fp16 copy for gather
__device__ static int g_cnt   [MAX_NODES];
__device__ static int g_off   [MAX_NODES];
__device__ static int g_cursor[MAX_NODES];
__device__ static int g_ecol  [MAX_EDGES];
__device__ static int g_bsum  [1024];
__device__ int g_is64;

// ---------------------------------------------------------------------------
// Index dtype probe: int64 values < 1e5 have all-zero high words.
// ---------------------------------------------------------------------------
__global__ void detect_idx_kernel(const int* __restrict__ rows) {
    if (threadIdx.x == 0 && blockIdx.x == 0) {
        int all_hi_zero = 1;
        #pragma unroll 4
        for (int i = 0; i < 64; i++) {
            if (rows[2 * i + 1] != 0) { all_hi_zero = 0; break; }
        }
        g_is64 = all_hi_zero;
    }
}

__device__ __forceinline__ int load_idx(const void* p, int e) {
    return g_is64 ? (int)((const long long*)p)[e] : ((const int*)p)[e];
}

// ---------------------------------------------------------------------------
// CSR build: histogram -> 2-level exclusive scan -> fill
// ---------------------------------------------------------------------------
__global__ void __launch_bounds__(256) hist_kernel(const void* __restrict__ rows, int nE) {
    int e = blockIdx.x * 256 + threadIdx.x;
    if (e >= nE) return;
    atomicAdd(&g_cnt[load_idx(rows, e)], 1);
}

__global__ void __launch_bounds__(1024) scan1_kernel(int N) {
    __shared__ int sm[1024];
    int i = blockIdx.x * 1024 + threadIdx.x;
    int v = (i < N) ? g_cnt[i] : 0;
    sm[threadIdx.x] = v;
    __syncthreads();
    #pragma unroll
    for (int d = 1; d < 1024; d <<= 1) {
        int t = (threadIdx.x >= d) ? sm[threadIdx.x - d] : 0;
        __syncthreads();
        sm[threadIdx.x] += t;
        __syncthreads();
    }
    if (i < N) g_off[i] = sm[threadIdx.x] - v;       // exclusive
    if (threadIdx.x == 1023) g_bsum[blockIdx.x] = sm[1023];
}

__global__ void __launch_bounds__(1024) scan2_kernel(int nb) {
    __shared__ int sm[1024];
    int v = (threadIdx.x < nb) ? g_bsum[threadIdx.x] : 0;
    sm[threadIdx.x] = v;
    __syncthreads();
    #pragma unroll
    for (int d = 1; d < 1024; d <<= 1) {
        int t = (threadIdx.x >= d) ? sm[threadIdx.x - d] : 0;
        __syncthreads();
        sm[threadIdx.x] += t;
        __syncthreads();
    }
    if (threadIdx.x < nb) g_bsum[threadIdx.x] = sm[threadIdx.x] - v;  // exclusive
}

__global__ void __launch_bounds__(1024) scan3_kernel(int N) {
    int i = blockIdx.x * 1024 + threadIdx.x;
    if (i >= N) return;
    int o = g_off[i] + g_bsum[i >> 10];
    g_off[i] = o;
    g_cursor[i] = o;
}

__global__ void __launch_bounds__(256) fill_kernel(
    const void* __restrict__ rows, const void* __restrict__ cols, int nE)
{
    int e = blockIdx.x * 256 + threadIdx.x;
    if (e >= nE) return;
    int r = load_idx(rows, e);
    int c = load_idx(cols, e);
    int p = atomicAdd(&g_cursor[r], 1);
    g_ecol[p] = c;
}

// ---------------------------------------------------------------------------
// tf32 helpers
// ---------------------------------------------------------------------------
__device__ __forceinline__ float to_tf32(float a) {
    float r;
    asm("cvt.rna.tf32.f32 %0, %1;" : "=f"(r) : "f"(a));
    return r;
}

__device__ __forceinline__ void mma_tf32(
    float& d0, float& d1, float& d2, float& d3,
    uint32_t a0, uint32_t a1, uint32_t a2, uint32_t a3,
    uint32_t b0, uint32_t b1)
{
    asm volatile(
        "mma.sync.aligned.m16n8k8.row.col.f32.tf32.tf32.f32 "
        "{%0,%1,%2,%3}, {%4,%5,%6,%7}, {%8,%9}, {%0,%1,%2,%3};"
        : "+f"(d0), "+f"(d1), "+f"(d2), "+f"(d3)
        : "r"(a0), "r"(a1), "r"(a2), "r"(a3), "r"(b0), "r"(b1));
}

// ---------------------------------------------------------------------------
// S/I = sigmoid(x[s] @ W^T + b) on tensor cores (mma.sync tf32).
// Block: 64 nodes x 128 outputs, 256 threads = 8 warps (4 along M x 2 along O).
// A frags from xt[node][k] (pitch 132); B frags read row-major W[n][k]
// directly (pitch 132) -- both conflict-free.  s==1 also emits fp16 I copy.
// ---------------------------------------------------------------------------
__global__ void __launch_bounds__(256) gemm_sigmoid_kernel(
    const float* __restrict__ x, const float* __restrict__ W,
    const float* __restrict__ b, int N)
{
    const int s = blockIdx.y;
    const float* __restrict__ xg = x + (size_t)s * N * H;
    float* __restrict__ out = (s == 0) ? g_S : g_I;

    extern __shared__ float sm[];
    float* xt = sm;                 // 64 * XPITCH
    float* Ws = sm + 64 * XPITCH;   // 128 * WPITCH (row-major W, tf32-rounded)

    const int tid = threadIdx.x;
    const int n0 = blockIdx.x * 64;

    // Load x tile (64 nodes x 128), tf32-rounded, zero-padded past N
    for (int i = tid; i < 64 * 32; i += 256) {
        int n = i >> 5;
        int q = i & 31;
        float4 v = make_float4(0.f, 0.f, 0.f, 0.f);
        if (n0 + n < N)
            v = __ldcs((const float4*)(xg + (size_t)(n0 + n) * H) + q);
        v.x = to_tf32(v.x); v.y = to_tf32(v.y);
        v.z = to_tf32(v.z); v.w = to_tf32(v.w);
        ((float4*)(xt + n * XPITCH))[q] = v;
    }
    // Load W (row-major [o][h]) -> Ws row-major, tf32-rounded
    for (int i = tid; i < 128 * 32; i += 256) {
        int o = i >> 5;
        int q = i & 31;
        float4 v = ((const float4*)W)[o * 32 + q];
        v.x = to_tf32(v.x); v.y = to_tf32(v.y);
        v.z = to_tf32(v.z); v.w = to_tf32(v.w);
        ((float4*)(Ws + o * WPITCH))[q] = v;
    }
    __syncthreads();

    const int wid  = tid >> 5;
    const int lane = tid & 31;
    const int g = lane >> 2;        // groupID
    const int c = lane & 3;         // threadID_in_group
    const int m0 = (wid & 3) * 16;  // warp's 16-node row block
    const int o0 = (wid >> 2) * 64; // warp's 64-output block

    float acc[8][4];
    #pragma unroll
    for (int t = 0; t < 8; t++)
        #pragma unroll
        for (int k = 0; k < 4; k++) acc[t][k] = 0.f;

    const uint32_t* xa = (const uint32_t*)(xt + (m0 + g) * XPITCH + c);
    const uint32_t* wa = (const uint32_t*)(Ws + (o0 + g) * WPITCH + c);

    #pragma unroll
    for (int kk = 0; kk < H; kk += 8) {
        // A fragment: rows (m0+g, m0+g+8), cols (kk+c, kk+c+4)
        const uint32_t a0 = xa[kk];
        const uint32_t a1 = xa[8 * XPITCH + kk];
        const uint32_t a2 = xa[kk + 4];
        const uint32_t a3 = xa[8 * XPITCH + kk + 4];
        #pragma unroll
        for (int nt = 0; nt < 8; nt++) {
            // B fragment: B[k][n] = W[n][k]; b0=W[o0+nt*8+g][kk+c], b1=+4
            const uint32_t b0 = wa[nt * 8 * WPITCH + kk];
            const uint32_t b1 = wa[nt * 8 * WPITCH + kk + 4];
            mma_tf32(acc[nt][0], acc[nt][1], acc[nt][2], acc[nt][3],
                     a0, a1, a2, a3, b0, b1);
        }
    }

    // Epilogue: bias + sigmoid + store (c0,c1 -> row g; c2,c3 -> row g+8)
    const int node0 = n0 + m0 + g;
    const int node1 = node0 + 8;
    #pragma unroll
    for (int nt = 0; nt < 8; nt++) {
        const int o = o0 + nt * 8 + 2 * c;
        const float2 bb = *(const float2*)(b + o);
        float r0 = 1.f / (1.f + __expf(-(acc[nt][0] + bb.x)));
        float r1 = 1.f / (1.f + __expf(-(acc[nt][1] + bb.y)));
        float r2 = 1.f / (1.f + __expf(-(acc[nt][2] + bb.x)));
        float r3 = 1.f / (1.f + __expf(-(acc[nt][3] + bb.y)));
        if (node0 < N) {
            __stcs((float2*)(out + (size_t)node0 * H + o), make_float2(r0, r1));
            if (s == 1) {
                __half2 hv = __floats2half2_rn(r0, r1);
                *(__half2*)(g_Ih + (size_t)node0 * H + o) = hv;
            }
        }
        if (node1 < N) {
            __stcs((float2*)(out + (size_t)node1 * H + o), make_float2(r2, r3));
            if (s == 1) {
                __half2 hv = __floats2half2_rn(r2, r3);
                *(__half2*)(g_Ih + (size_t)node1 * H + o) = hv;
            }
        }
    }
}

// ---------------------------------------------------------------------------
// Fused gather + epilogue: one warp per destination row.  AI accumulated in
// registers from the fp16 I copy; dS/dI/dR streamed out evict-first.
// ---------------------------------------------------------------------------
__global__ void __launch_bounds__(256) gather_epilogue_kernel(
    const float* __restrict__ x, float* __restrict__ out, int N)
{
    const int g = blockIdx.x * 256 + threadIdx.x;
    const int row = g >> 5;
    const int lane = g & 31;
    if (row >= N) return;

    const int start = g_off[row];
    const int deg   = g_cnt[row];
    const uint2* __restrict__ Ih = (const uint2*)g_Ih;   // 32 uint2 per row

    float4 ai = make_float4(0.f, 0.f, 0.f, 0.f);
    int e = 0;
    for (; e + 4 <= deg; e += 4) {
        const int c0 = __ldcs(&g_ecol[start + e + 0]);
        const int c1 = __ldcs(&g_ecol[start + e + 1]);
        const int c2 = __ldcs(&g_ecol[start + e + 2]);
        const int c3 = __ldcs(&g_ecol[start + e + 3]);
        const uint2 v0 = Ih[(size_t)c0 * 32 + lane];
        const uint2 v1 = Ih[(size_t)c1 * 32 + lane];
        const uint2 v2 = Ih[(size_t)c2 * 32 + lane];
        const uint2 v3 = Ih[(size_t)c3 * 32 + lane];
        #pragma unroll
        for (int k = 0; k < 4; k++) {
            const uint2 v = (k == 0) ? v0 : (k == 1) ? v1 : (k == 2) ? v2 : v3;
            const float2 f0 = __half22float2(*(const __half2*)&v.x);
            const float2 f1 = __half22float2(*(const __half2*)&v.y);
            ai.x += f0.x; ai.y += f0.y; ai.z += f1.x; ai.w += f1.y;
        }
    }
    for (; e < deg; e++) {
        const int c = __ldcs(&g_ecol[start + e]);
        const uint2 v = Ih[(size_t)c * 32 + lane];
        const float2 f0 = __half22float2(*(const __half2*)&v.x);
        const float2 f1 = __half22float2(*(const __half2*)&v.y);
        ai.x += f0.x; ai.y += f0.y; ai.z += f1.x; ai.w += f1.y;
    }

    const float* x3 = x + (size_t)3 * N * H + (size_t)row * H;
    const float beta  = x3[0];
    const float gamma = x3[1];

    const size_t r32 = (size_t)row * 32 + lane;
    const float4 sv = __ldcs((const float4*)g_S + r32);
    const float4 iv = __ldcs((const float4*)g_I + r32);

    float4 dS, dI, dR;
    dS.x = -beta * ai.x * sv.x;  dS.y = -beta * ai.y * sv.y;
    dS.z = -beta * ai.z * sv.z;  dS.w = -beta * ai.w * sv.w;
    dR.x = gamma * iv.x;  dR.y = gamma * iv.y;
    dR.z = gamma * iv.z;  dR.w = gamma * iv.w;
    dI.x = -dS.x - dR.x;  dI.y = -dS.y - dR.y;
    dI.z = -dS.z - dR.z;  dI.w = -dS.w - dR.w;

    const size_t NH4 = (size_t)N * 32;
    float4* o4 = (float4*)out;
    __stcs(o4 + r32,           dS);
    __stcs(o4 + NH4 + r32,     dI);
    __stcs(o4 + 2 * NH4 + r32, dR);
    __stcs(o4 + 3 * NH4 + r32, make_float4(0.f, 0.f, 0.f, 0.f));
}

// ---------------------------------------------------------------------------
extern "C" void kernel_launch(void* const* d_in, const int* in_sizes, int n_in,
                              void* d_out, int out_size)
{
    const float* x    = (const float*)d_in[0];
    const float* W    = (const float*)d_in[1];
    const float* b    = (const float*)d_in[2];
    const void*  rows = d_in[3];
    const void*  cols = d_in[4];

    const int N  = in_sizes[0] / (4 * H);
    const int nE = in_sizes[3];

    void* cntPtr = nullptr;
    cudaGetSymbolAddress(&cntPtr, g_cnt);
    cudaMemsetAsync(cntPtr, 0, (size_t)N * sizeof(int));

    detect_idx_kernel<<<1, 32>>>((const int*)rows);           // kernel 1

    const int eb = (nE + 255) / 256;
    const int nb = (N + 1023) / 1024;
    hist_kernel<<<eb, 256>>>(rows, nE);                       // kernel 2
    scan1_kernel<<<nb, 1024>>>(N);                            // kernel 3

    // MMA GEMM at kernel slot 4 (the profiled slot)
    const int smem_bytes = (64 * XPITCH + 128 * WPITCH) * (int)sizeof(float);
    cudaFuncSetAttribute(gemm_sigmoid_kernel,
                         cudaFuncAttributeMaxDynamicSharedMemorySize, smem_bytes);
    dim3 ggrid((N + 63) / 64, 2);
    gemm_sigmoid_kernel<<<ggrid, 256, smem_bytes>>>(x, W, b, N);

    scan2_kernel<<<1, 1024>>>(nb);
    scan3_kernel<<<nb, 1024>>>(N);
    fill_kernel<<<eb, 256>>>(rows, cols, nE);

    const long long gt = (long long)N * 32;
    gather_epilogue_kernel<<<(int)((gt + 255) / 256), 256>>>(x, (float*)d_out, N);
}